// round 7
// baseline (speedup 1.0000x reference)
#include <cuda_runtime.h>
#include <cuda_bf16.h>
#include <math.h>
#include <cstdint>

// Problem constants (LocalAttention: B=4, T=2048, C=1024, WIN=16)
#define TT   2048
#define CC   1024
#define HALF 8
#define WW   17
#define MM   8192

// GEMM tiling
#define BM 128
#define BN 128
#define BKK 32                   // bf16 K elems per stage
#define NIT (CC / BKK)           // 32 k-iterations
#define TILE_B  8192             // 128 rows x 32 bf16 x 2B
#define STAGE_B (4 * TILE_B)     // Ahi, Alo, Bhi, Blo
#define GEMM_SMEM (4 * STAGE_B)  // 4 stages = 131072
#define GRID_PERSIST 148

// ---------------------------------------------------------------------------
// Scratch (device globals: allocation-free rule)
// ---------------------------------------------------------------------------
__device__ float g_q[MM * CC];
__device__ float g_k[MM * CC];
__device__ float g_v[MM * CC];
__device__ __nv_bfloat16 g_x_hi[MM * CC];
__device__ __nv_bfloat16 g_x_lo[MM * CC];
__device__ __nv_bfloat16 g_ctx_hi[MM * CC];
__device__ __nv_bfloat16 g_ctx_lo[MM * CC];
__device__ __nv_bfloat16 g_w_hi[4 * CC * CC];   // Wq, Wk, Wv, Wo
__device__ __nv_bfloat16 g_w_lo[4 * CC * CC];

// ---------------------------------------------------------------------------
// PTX helpers (sm_80+ base-target instructions only)
// ---------------------------------------------------------------------------
__device__ __forceinline__ uint32_t smem_u32(const void* p) {
    uint32_t a;
    asm("{ .reg .u64 t; cvta.to.shared.u64 t, %1; cvt.u32.u64 %0, t; }" : "=r"(a) : "l"(p));
    return a;
}
__device__ __forceinline__ void cp_async16(uint32_t dst, const void* src) {
    asm volatile("cp.async.cg.shared.global [%0], [%1], 16;" :: "r"(dst), "l"(src));
}
__device__ __forceinline__ void cp_commit() { asm volatile("cp.async.commit_group;"); }
template <int N>
__device__ __forceinline__ void cp_wait() { asm volatile("cp.async.wait_group %0;" :: "n"(N)); }

__device__ __forceinline__ void ldsm_x4(uint32_t& r0, uint32_t& r1, uint32_t& r2, uint32_t& r3,
                                        uint32_t addr) {
    asm volatile("ldmatrix.sync.aligned.m8n8.x4.shared.b16 {%0,%1,%2,%3}, [%4];"
                 : "=r"(r0), "=r"(r1), "=r"(r2), "=r"(r3) : "r"(addr));
}
__device__ __forceinline__ void mma_bf16(float* d, const uint32_t* a, uint32_t b0, uint32_t b1) {
    asm volatile(
        "mma.sync.aligned.m16n8k16.row.col.f32.bf16.bf16.f32 "
        "{%0,%1,%2,%3}, {%4,%5,%6,%7}, {%8,%9}, {%0,%1,%2,%3};"
        : "+f"(d[0]), "+f"(d[1]), "+f"(d[2]), "+f"(d[3])
        : "r"(a[0]), "r"(a[1]), "r"(a[2]), "r"(a[3]), "r"(b0), "r"(b1));
}

// Swizzle on 64B logical rows (conflict-free ldmatrix + STS16)
#define SWZ(off) ((off) ^ (((off) >> 3) & 0x70))

__device__ __forceinline__ uint32_t ldsm_addr(uint32_t tile_base, int row0, int chunk0, int lane) {
    int row   = row0 + (lane & 15);
    int chunk = chunk0 + (lane >> 4);
    uint32_t off = (uint32_t)row * 64 + (uint32_t)chunk * 16;
    return tile_base + SWZ(off);
}

// ---------------------------------------------------------------------------
// fp32 -> bf16 hi/lo split. blockIdx.y selects among up to 3 sources.
// ---------------------------------------------------------------------------
__global__ __launch_bounds__(256)
void split_bf16(const float* __restrict__ s0, const float* __restrict__ s1,
                const float* __restrict__ s2,
                __nv_bfloat16* __restrict__ hi, __nv_bfloat16* __restrict__ lo, int n4)
{
    const int w = blockIdx.y;
    const float* src = (w == 0) ? s0 : ((w == 1) ? s1 : s2);
    int i = blockIdx.x * blockDim.x + threadIdx.x;
    if (i >= n4) return;
    float4 v = ((const float4*)src)[i];
    float f[4] = {v.x, v.y, v.z, v.w};
    __nv_bfloat16 h[4], l[4];
#pragma unroll
    for (int j = 0; j < 4; j++) {
        h[j] = __float2bfloat16(f[j]);
        l[j] = __float2bfloat16(f[j] - __bfloat162float(h[j]));
    }
    const size_t o = (size_t)w * n4 + i;
    ((ushort4*)hi)[o] = make_ushort4(*(unsigned short*)&h[0], *(unsigned short*)&h[1],
                                     *(unsigned short*)&h[2], *(unsigned short*)&h[3]);
    ((ushort4*)lo)[o] = make_ushort4(*(unsigned short*)&l[0], *(unsigned short*)&l[1],
                                     *(unsigned short*)&l[2], *(unsigned short*)&l[3]);
}

// ---------------------------------------------------------------------------
// Persistent bf16x3 NT GEMM with register-fragment double buffering.
// out[m,n] = sum_k A[m,k]*W[n,k] + bias[n]; 128x128 tile, 8 warps (4Mx2N),
// 4-stage cp.async (BK=32), frags for k16 step g+1 prefetched during MMAs of g.
// ---------------------------------------------------------------------------
__global__ __launch_bounds__(256, 1)
void gemm_bf16x3(const __nv_bfloat16* __restrict__ Ahi, const __nv_bfloat16* __restrict__ Alo,
                 const __nv_bfloat16* __restrict__ Whi, const __nv_bfloat16* __restrict__ Wlo,
                 const float* __restrict__ b0, const float* __restrict__ b1,
                 const float* __restrict__ b2,
                 float* __restrict__ o0, float* __restrict__ o1, float* __restrict__ o2,
                 int ntiles, int nblk)
{
    extern __shared__ char sm[];
    const uint32_t sbase = smem_u32(sm);
    const int tid   = threadIdx.x;
    const int lane  = tid & 31;
    const int warp  = tid >> 5;
    const int warpM = warp >> 1;
    const int warpN = warp & 1;

    const int lrow = tid >> 1;
    const int lc0  = (tid & 1) * 2;
    uint32_t dphys[2];
#pragma unroll
    for (int i = 0; i < 2; i++) {
        uint32_t off = (uint32_t)lrow * 64 + (uint32_t)(lc0 + i) * 16;
        dphys[i] = SWZ(off);
    }

    // Fragment double buffers
    uint32_t afr[2][2][2][4];   // [buf][mt][hl][reg]
    uint32_t bfr[2][2][4][4];   // [buf][hl][gp][reg]

#define ISSUE_STAGE(s, kc) do { \
    uint32_t stg_ = sbase + (uint32_t)(s) * STAGE_B; \
    _Pragma("unroll") \
    for (int t_ = 0; t_ < 4; t_++) { \
        _Pragma("unroll") \
        for (int i_ = 0; i_ < 2; i_++) { \
            cp_async16(stg_ + t_ * TILE_B + dphys[i_], gsrc[t_] + (kc) + (lc0 + i_) * 8); \
        } \
    } \
    cp_commit(); \
} while (0)

#define LOAD_FRAGS(buf, stg, g) do { \
    _Pragma("unroll") \
    for (int mt_ = 0; mt_ < 2; mt_++) { \
        _Pragma("unroll") \
        for (int hl_ = 0; hl_ < 2; hl_++) { \
            uint32_t ad_ = ldsm_addr((stg) + hl_ * TILE_B, warpM * 32 + mt_ * 16, 2 * (g), lane); \
            ldsm_x4(afr[buf][mt_][hl_][0], afr[buf][mt_][hl_][1], \
                    afr[buf][mt_][hl_][2], afr[buf][mt_][hl_][3], ad_); \
        } \
    } \
    _Pragma("unroll") \
    for (int hl_ = 0; hl_ < 2; hl_++) { \
        _Pragma("unroll") \
        for (int gp_ = 0; gp_ < 4; gp_++) { \
            uint32_t ad_ = ldsm_addr((stg) + (2 + hl_) * TILE_B, warpN * 64 + gp_ * 16, 2 * (g), lane); \
            ldsm_x4(bfr[buf][hl_][gp_][0], bfr[buf][hl_][gp_][1], \
                    bfr[buf][hl_][gp_][2], bfr[buf][hl_][gp_][3], ad_); \
        } \
    } \
} while (0)

#define MMA_STEP(buf) do { \
    _Pragma("unroll") \
    for (int mt_ = 0; mt_ < 2; mt_++) { \
        _Pragma("unroll") \
        for (int gp_ = 0; gp_ < 4; gp_++) { \
            mma_bf16(acc[mt_][gp_ * 2 + 0], afr[buf][mt_][0], bfr[buf][0][gp_][0], bfr[buf][0][gp_][2]); \
            mma_bf16(acc[mt_][gp_ * 2 + 1], afr[buf][mt_][0], bfr[buf][0][gp_][1], bfr[buf][0][gp_][3]); \
            mma_bf16(acc[mt_][gp_ * 2 + 0], afr[buf][mt_][0], bfr[buf][1][gp_][0], bfr[buf][1][gp_][2]); \
            mma_bf16(acc[mt_][gp_ * 2 + 1], afr[buf][mt_][0], bfr[buf][1][gp_][1], bfr[buf][1][gp_][3]); \
            mma_bf16(acc[mt_][gp_ * 2 + 0], afr[buf][mt_][1], bfr[buf][0][gp_][0], bfr[buf][0][gp_][2]); \
            mma_bf16(acc[mt_][gp_ * 2 + 1], afr[buf][mt_][1], bfr[buf][0][gp_][1], bfr[buf][0][gp_][3]); \
        } \
    } \
} while (0)

    for (int tile = blockIdx.x; tile < ntiles; tile += gridDim.x) {
        const int mb = tile / nblk;
        const int nb = tile - mb * nblk;
        const int bm = mb * BM;
        const int which = nb >> 3;
        const int col0  = (nb & 7) * BN;
        const float* bias = (which == 0) ? b0 : ((which == 1) ? b1 : b2);
        float* Cout       = (which == 0) ? o0 : ((which == 1) ? o1 : o2);

        const __nv_bfloat16* gsrc[4] = {
            Ahi + (size_t)(bm + lrow) * CC,
            Alo + (size_t)(bm + lrow) * CC,
            Whi + (size_t)(nb * BN + lrow) * CC,
            Wlo + (size_t)(nb * BN + lrow) * CC
        };

        float acc[2][8][4];
#pragma unroll
        for (int mt = 0; mt < 2; mt++)
#pragma unroll
            for (int nt = 0; nt < 8; nt++)
#pragma unroll
                for (int r = 0; r < 4; r++) acc[mt][nt][r] = 0.f;

        ISSUE_STAGE(0, 0);
        ISSUE_STAGE(1, 32);
        ISSUE_STAGE(2, 64);
        cp_wait<2>();
        __syncthreads();
        LOAD_FRAGS(0, sbase + 0 * STAGE_B, 0);   // stage 0, k16 step 0

        for (int it = 0; it < NIT; it++) {
            const uint32_t stg = sbase + (uint32_t)(it & 3) * STAGE_B;
            // Prefetch second k16 step of this stage, then MMA first step.
            LOAD_FRAGS(1, stg, 1);
            if (it + 3 < NIT) { ISSUE_STAGE((it + 3) & 3, (it + 3) * BKK); }
            else              { cp_commit(); }
            MMA_STEP(0);
            // Advance to next stage; prefetch its first k16 step, then MMA second.
            if (it + 1 < NIT) {
                cp_wait<2>();
                __syncthreads();
                LOAD_FRAGS(0, sbase + (uint32_t)((it + 1) & 3) * STAGE_B, 0);
            }
            MMA_STEP(1);
        }

        // Epilogue: bias + fp32 store
#pragma unroll
        for (int mt = 0; mt < 2; mt++) {
            const int row0 = bm + warpM * 32 + mt * 16 + (lane >> 2);
#pragma unroll
            for (int nt = 0; nt < 8; nt++) {
                const int col = col0 + warpN * 64 + nt * 8 + (lane & 3) * 2;
                const float c0 = bias[col], c1 = bias[col + 1];
                float2 v0 = make_float2(acc[mt][nt][0] + c0, acc[mt][nt][1] + c1);
                float2 v1 = make_float2(acc[mt][nt][2] + c0, acc[mt][nt][3] + c1);
                *(float2*)(Cout + (size_t)row0 * CC + col)       = v0;
                *(float2*)(Cout + (size_t)(row0 + 8) * CC + col) = v1;
            }
        }
    }
#undef ISSUE_STAGE
#undef LOAD_FRAGS
#undef MMA_STEP
}

// ---------------------------------------------------------------------------
// Local windowed attention; writes ctx directly as bf16 hi/lo pair.
// ---------------------------------------------------------------------------
__global__ __launch_bounds__(128)
void local_attn(const float* __restrict__ q, const float* __restrict__ k,
                const float* __restrict__ v,
                __nv_bfloat16* __restrict__ ch, __nv_bfloat16* __restrict__ cl)
{
    const int bt   = blockIdx.x;
    const int t    = bt & (TT - 1);
    const int tid  = threadIdx.x;
    const int warp = tid >> 5;
    const int lane = tid & 31;

    __shared__ float red[WW][4];
    __shared__ float wgt[WW];

    const float* qrow = q + (size_t)bt * CC;
    float qreg[8];
#pragma unroll
    for (int i = 0; i < 8; i++) qreg[i] = qrow[tid + i * 128];

#pragma unroll
    for (int w = 0; w < WW; w++) {
        const int dt = w - HALF;
        const int tt = t + dt;
        float p = 0.f;
        if (tt >= 0 && tt < TT) {
            const float* krow = k + (size_t)(bt + dt) * CC;
#pragma unroll
            for (int i = 0; i < 8; i++) p += qreg[i] * krow[tid + i * 128];
        }
#pragma unroll
        for (int o = 16; o; o >>= 1) p += __shfl_xor_sync(0xffffffffu, p, o);
        if (lane == 0) red[w][warp] = p;
    }
    __syncthreads();

    if (tid == 0) {
        float s[WW];
        float mx = -1e30f;
#pragma unroll
        for (int w = 0; w < WW; w++) {
            const int tt = t + w - HALF;
            if (tt >= 0 && tt < TT) {
                s[w] = (red[w][0] + red[w][1] + red[w][2] + red[w][3]) * 0.03125f;
                mx = fmaxf(mx, s[w]);
            } else {
                s[w] = -3.0e38f;
            }
        }
        float sum = 0.f;
#pragma unroll
        for (int w = 0; w < WW; w++) {
            float e = (s[w] > -1.0e38f) ? expf(s[w] - mx) : 0.f;
            wgt[w] = e;
            sum += e;
        }
        const float inv = 1.f / sum;
#pragma unroll
        for (int w = 0; w < WW; w++) wgt[w] *= inv;
    }
    __syncthreads();

    float acc[8];
#pragma unroll
    for (int i = 0; i < 8; i++) acc[i] = 0.f;

#pragma unroll
    for (int w = 0; w < WW; w++) {
        const int dt = w - HALF;
        const int tt = t + dt;
        if (tt < 0 || tt >= TT) continue;
        const float a = wgt[w];
        const float* vrow = v + (size_t)(bt + dt) * CC;
#pragma unroll
        for (int i = 0; i < 8; i++) acc[i] += a * vrow[tid + i * 128];
    }

    __nv_bfloat16* hrow = ch + (size_t)bt * CC;
    __nv_bfloat16* lrow = cl + (size_t)bt * CC;
#pragma unroll
    for (int i = 0; i < 8; i++) {
        __nv_bfloat16 h = __float2bfloat16(acc[i]);
        __nv_bfloat16 l = __float2bfloat16(acc[i] - __bfloat162float(h));
        hrow[tid + i * 128] = h;
        lrow[tid + i * 128] = l;
    }
}

// ---------------------------------------------------------------------------
// Launch (6 launches; indices 3 and 5 are the GEMMs, for ncu capture)
// ---------------------------------------------------------------------------
extern "C" void kernel_launch(void* const* d_in, const int* in_sizes, int n_in,
                              void* d_out, int out_size)
{
    const float* x  = (const float*)d_in[0];
    const float* Wq = (const float*)d_in[1];
    const float* bq = (const float*)d_in[2];
    const float* Wk = (const float*)d_in[3];
    const float* bk = (const float*)d_in[4];
    const float* Wv = (const float*)d_in[5];
    const float* bv = (const float*)d_in[6];
    const float* Wo = (const float*)d_in[7];
    const float* bo = (const float*)d_in[8];

    float *q, *k, *v;
    __nv_bfloat16 *xh, *xl, *ch, *cl, *wh, *wl;
    cudaGetSymbolAddress((void**)&q,   g_q);
    cudaGetSymbolAddress((void**)&k,   g_k);
    cudaGetSymbolAddress((void**)&v,   g_v);
    cudaGetSymbolAddress((void**)&xh,  g_x_hi);
    cudaGetSymbolAddress((void**)&xl,  g_x_lo);
    cudaGetSymbolAddress((void**)&ch,  g_ctx_hi);
    cudaGetSymbolAddress((void**)&cl,  g_ctx_lo);
    cudaGetSymbolAddress((void**)&wh,  g_w_hi);
    cudaGetSymbolAddress((void**)&wl,  g_w_lo);

    cudaFuncSetAttribute(gemm_bf16x3, cudaFuncAttributeMaxDynamicSharedMemorySize, GEMM_SMEM);

    const int nx4 = MM * CC / 4;
    const int nw4 = CC * CC / 4;
    const size_t WSZ = (size_t)CC * CC;

    // 0: split x
    split_bf16<<<dim3(nx4 / 256, 1), 256>>>(x, x, x, xh, xl, nx4);
    // 1: split Wq, Wk, Wv  -> wh/wl segments 0..2
    split_bf16<<<dim3(nw4 / 256, 3), 256>>>(Wq, Wk, Wv, wh, wl, nw4);
    // 2: split Wo -> segment 3
    split_bf16<<<dim3(nw4 / 256, 1), 256>>>(Wo, Wo, Wo, wh + 3 * WSZ, wl + 3 * WSZ, nw4);
    // 3: fused QKV GEMM (persistent, 1536 tiles, nblk=24)
    gemm_bf16x3<<<GRID_PERSIST, 256, GEMM_SMEM>>>(xh, xl, wh, wl,
                                                  bq, bk, bv, q, k, v,
                                                  (MM / BM) * 24, 24);
    // 4: attention (writes ctx hi/lo)
    local_attn<<<MM, 128>>>(q, k, v, ch, cl);
    // 5: output projection (persistent, 512 tiles, nblk=8)
    gemm_bf16x3<<<GRID_PERSIST, 256, GEMM_SMEM>>>(ch, cl, wh + 3 * WSZ, wl + 3 * WSZ,
                                                  bo, bo, bo,
                                                  (float*)d_out, (float*)d_out, (float*)d_out,
                                                  (MM / BM) * 8, 8);
}

// round 8
// speedup vs baseline: 1.3809x; 1.3809x over previous
#include <cuda_runtime.h>
#include <cuda_bf16.h>
#include <math.h>
#include <cstdint>

// Problem constants (LocalAttention: B=4, T=2048, C=1024, WIN=16)
#define TT   2048
#define CC   1024
#define HALF 8
#define WW   17
#define MM   8192

// GEMM tiling: CTA tile 128x64, warp tile 32x32, 8 warps (4M x 2N)
#define BM 128
#define BN 64
#define BKK 32                    // bf16 K elems per stage
#define NIT (CC / BKK)            // 32 k-iterations
#define ATILE_B 8192              // 128 rows x 32 bf16 x 2B
#define BTILE_B 4096              // 64 rows x 32 bf16 x 2B
#define STAGE_B (2 * ATILE_B + 2 * BTILE_B)   // 24576
#define GEMM_SMEM (4 * STAGE_B)   // 98304
#define GRID_PERSIST 296          // 2 CTAs per SM

// ---------------------------------------------------------------------------
// Scratch (device globals: allocation-free rule)
// ---------------------------------------------------------------------------
__device__ float g_q[MM * CC];
__device__ float g_k[MM * CC];
__device__ float g_v[MM * CC];
__device__ __nv_bfloat16 g_x_hi[MM * CC];
__device__ __nv_bfloat16 g_x_lo[MM * CC];
__device__ __nv_bfloat16 g_ctx_hi[MM * CC];
__device__ __nv_bfloat16 g_ctx_lo[MM * CC];
__device__ __nv_bfloat16 g_w_hi[4 * CC * CC];   // Wq, Wk, Wv, Wo
__device__ __nv_bfloat16 g_w_lo[4 * CC * CC];

// ---------------------------------------------------------------------------
// PTX helpers (sm_80+ base-target instructions only)
// ---------------------------------------------------------------------------
__device__ __forceinline__ uint32_t smem_u32(const void* p) {
    uint32_t a;
    asm("{ .reg .u64 t; cvta.to.shared.u64 t, %1; cvt.u32.u64 %0, t; }" : "=r"(a) : "l"(p));
    return a;
}
__device__ __forceinline__ void cp_async16(uint32_t dst, const void* src) {
    asm volatile("cp.async.cg.shared.global [%0], [%1], 16;" :: "r"(dst), "l"(src));
}
__device__ __forceinline__ void cp_commit() { asm volatile("cp.async.commit_group;"); }
template <int N>
__device__ __forceinline__ void cp_wait() { asm volatile("cp.async.wait_group %0;" :: "n"(N)); }

__device__ __forceinline__ void ldsm_x4(uint32_t& r0, uint32_t& r1, uint32_t& r2, uint32_t& r3,
                                        uint32_t addr) {
    asm volatile("ldmatrix.sync.aligned.m8n8.x4.shared.b16 {%0,%1,%2,%3}, [%4];"
                 : "=r"(r0), "=r"(r1), "=r"(r2), "=r"(r3) : "r"(addr));
}
__device__ __forceinline__ void mma_bf16(float* d, const uint32_t* a, uint32_t b0, uint32_t b1) {
    asm volatile(
        "mma.sync.aligned.m16n8k16.row.col.f32.bf16.bf16.f32 "
        "{%0,%1,%2,%3}, {%4,%5,%6,%7}, {%8,%9}, {%0,%1,%2,%3};"
        : "+f"(d[0]), "+f"(d[1]), "+f"(d[2]), "+f"(d[3])
        : "r"(a[0]), "r"(a[1]), "r"(a[2]), "r"(a[3]), "r"(b0), "r"(b1));
}

// Swizzle on 64B logical rows (conflict-free ldmatrix + STS16)
#define SWZ(off) ((off) ^ (((off) >> 3) & 0x70))

__device__ __forceinline__ uint32_t ldsm_addr(uint32_t tile_base, int row0, int chunk0, int lane) {
    int row   = row0 + (lane & 15);
    int chunk = chunk0 + (lane >> 4);
    uint32_t off = (uint32_t)row * 64 + (uint32_t)chunk * 16;
    return tile_base + SWZ(off);
}

// ---------------------------------------------------------------------------
// fp32 -> bf16 hi/lo split. blockIdx.y selects among up to 3 sources.
// ---------------------------------------------------------------------------
__global__ __launch_bounds__(256)
void split_bf16(const float* __restrict__ s0, const float* __restrict__ s1,
                const float* __restrict__ s2,
                __nv_bfloat16* __restrict__ hi, __nv_bfloat16* __restrict__ lo, int n4)
{
    const int w = blockIdx.y;
    const float* src = (w == 0) ? s0 : ((w == 1) ? s1 : s2);
    int i = blockIdx.x * blockDim.x + threadIdx.x;
    if (i >= n4) return;
    float4 v = ((const float4*)src)[i];
    float f[4] = {v.x, v.y, v.z, v.w};
    __nv_bfloat16 h[4], l[4];
#pragma unroll
    for (int j = 0; j < 4; j++) {
        h[j] = __float2bfloat16(f[j]);
        l[j] = __float2bfloat16(f[j] - __bfloat162float(h[j]));
    }
    const size_t o = (size_t)w * n4 + i;
    ((ushort4*)hi)[o] = make_ushort4(*(unsigned short*)&h[0], *(unsigned short*)&h[1],
                                     *(unsigned short*)&h[2], *(unsigned short*)&h[3]);
    ((ushort4*)lo)[o] = make_ushort4(*(unsigned short*)&l[0], *(unsigned short*)&l[1],
                                     *(unsigned short*)&l[2], *(unsigned short*)&l[3]);
}

// ---------------------------------------------------------------------------
// Persistent bf16x3 NT GEMM, 128x64 CTA tile, 2 CTAs/SM.
// out[m,n] = sum_k A[m,k]*W[n,k] + bias[n].
// nblk = weight 64-col blocks (48 for fused QKV, 16 for Wo); which = nb>>4.
// ---------------------------------------------------------------------------
__global__ __launch_bounds__(256, 2)
void gemm_bf16x3(const __nv_bfloat16* __restrict__ Ahi, const __nv_bfloat16* __restrict__ Alo,
                 const __nv_bfloat16* __restrict__ Whi, const __nv_bfloat16* __restrict__ Wlo,
                 const float* __restrict__ b0, const float* __restrict__ b1,
                 const float* __restrict__ b2,
                 float* __restrict__ o0, float* __restrict__ o1, float* __restrict__ o2,
                 int ntiles, int nblk)
{
    extern __shared__ char sm[];
    const uint32_t sbase = smem_u32(sm);
    const int tid   = threadIdx.x;
    const int lane  = tid & 31;
    const int warp  = tid >> 5;
    const int warpM = warp >> 1;     // 0..3 -> 32-row slice
    const int warpN = warp & 1;      // 0..1 -> 32-col slice

    // A loader: row = tid/2 (128 rows), two 16B chunks at (tid&1)*2 + {0,1}
    const int larow = tid >> 1;
    const int lac0  = (tid & 1) * 2;
    uint32_t daphys[2];
#pragma unroll
    for (int i = 0; i < 2; i++) {
        uint32_t off = (uint32_t)larow * 64 + (uint32_t)(lac0 + i) * 16;
        daphys[i] = SWZ(off);
    }
    // B loader: row = tid/4 (64 rows), one 16B chunk at tid&3
    const int lbrow = tid >> 2;
    const int lbc   = tid & 3;
    const uint32_t dbphys = SWZ((uint32_t)lbrow * 64 + (uint32_t)lbc * 16);

    for (int tile = blockIdx.x; tile < ntiles; tile += gridDim.x) {
        const int mb = tile / nblk;
        const int nb = tile - mb * nblk;
        const int bm = mb * BM;
        const int which = nb >> 4;
        const int col0  = (nb & 15) * BN;
        const float* bias = (which == 0) ? b0 : ((which == 1) ? b1 : b2);
        float* Cout       = (which == 0) ? o0 : ((which == 1) ? o1 : o2);

        const __nv_bfloat16* gA[2] = {
            Ahi + (size_t)(bm + larow) * CC,
            Alo + (size_t)(bm + larow) * CC
        };
        const __nv_bfloat16* gB[2] = {
            Whi + (size_t)(nb * BN + lbrow) * CC,
            Wlo + (size_t)(nb * BN + lbrow) * CC
        };

#define ISSUE_STAGE(s, kc) do { \
    uint32_t stg_ = sbase + (uint32_t)(s) * STAGE_B; \
    _Pragma("unroll") \
    for (int h_ = 0; h_ < 2; h_++) { \
        _Pragma("unroll") \
        for (int i_ = 0; i_ < 2; i_++) { \
            cp_async16(stg_ + h_ * ATILE_B + daphys[i_], gA[h_] + (kc) + (lac0 + i_) * 8); \
        } \
        cp_async16(stg_ + 2 * ATILE_B + h_ * BTILE_B + dbphys, gB[h_] + (kc) + lbc * 8); \
    } \
    cp_commit(); \
} while (0)

        float acc[2][4][4];
#pragma unroll
        for (int mt = 0; mt < 2; mt++)
#pragma unroll
            for (int nt = 0; nt < 4; nt++)
#pragma unroll
                for (int r = 0; r < 4; r++) acc[mt][nt][r] = 0.f;

        ISSUE_STAGE(0, 0);
        ISSUE_STAGE(1, 32);
        ISSUE_STAGE(2, 64);

        for (int it = 0; it < NIT; it++) {
            cp_wait<2>();
            __syncthreads();
            if (it + 3 < NIT) { ISSUE_STAGE((it + 3) & 3, (it + 3) * BKK); }
            else              { cp_commit(); }

            const uint32_t stg = sbase + (uint32_t)(it & 3) * STAGE_B;
#pragma unroll
            for (int g = 0; g < 2; g++) {        // two k16 steps per stage
                uint32_t afr[2][2][4];           // [mt][hl][reg]
#pragma unroll
                for (int mt = 0; mt < 2; mt++)
#pragma unroll
                    for (int hl = 0; hl < 2; hl++) {
                        uint32_t ad = ldsm_addr(stg + hl * ATILE_B,
                                                warpM * 32 + mt * 16, 2 * g, lane);
                        ldsm_x4(afr[mt][hl][0], afr[mt][hl][1], afr[mt][hl][2], afr[mt][hl][3], ad);
                    }
                uint32_t bfr[2][2][4];           // [hl][gp][reg]
#pragma unroll
                for (int hl = 0; hl < 2; hl++)
#pragma unroll
                    for (int gp = 0; gp < 2; gp++) {
                        uint32_t ad = ldsm_addr(stg + 2 * ATILE_B + hl * BTILE_B,
                                                warpN * 32 + gp * 16, 2 * g, lane);
                        ldsm_x4(bfr[hl][gp][0], bfr[hl][gp][1], bfr[hl][gp][2], bfr[hl][gp][3], ad);
                    }
#pragma unroll
                for (int mt = 0; mt < 2; mt++)
#pragma unroll
                    for (int gp = 0; gp < 2; gp++) {
                        mma_bf16(acc[mt][gp * 2 + 0], afr[mt][0], bfr[0][gp][0], bfr[0][gp][2]);
                        mma_bf16(acc[mt][gp * 2 + 1], afr[mt][0], bfr[0][gp][1], bfr[0][gp][3]);
                        mma_bf16(acc[mt][gp * 2 + 0], afr[mt][0], bfr[1][gp][0], bfr[1][gp][2]);
                        mma_bf16(acc[mt][gp * 2 + 1], afr[mt][0], bfr[1][gp][1], bfr[1][gp][3]);
                        mma_bf16(acc[mt][gp * 2 + 0], afr[mt][1], bfr[0][gp][0], bfr[0][gp][2]);
                        mma_bf16(acc[mt][gp * 2 + 1], afr[mt][1], bfr[0][gp][1], bfr[0][gp][3]);
                    }
            }
        }

        // Epilogue: bias + fp32 store (warp tile 32x32)
#pragma unroll
        for (int mt = 0; mt < 2; mt++) {
            const int row0 = bm + warpM * 32 + mt * 16 + (lane >> 2);
#pragma unroll
            for (int nt = 0; nt < 4; nt++) {
                const int col = col0 + warpN * 32 + nt * 8 + (lane & 3) * 2;
                const float c0 = bias[col], c1 = bias[col + 1];
                float2 v0 = make_float2(acc[mt][nt][0] + c0, acc[mt][nt][1] + c1);
                float2 v1 = make_float2(acc[mt][nt][2] + c0, acc[mt][nt][3] + c1);
                *(float2*)(Cout + (size_t)row0 * CC + col)       = v0;
                *(float2*)(Cout + (size_t)(row0 + 8) * CC + col) = v1;
            }
        }
#undef ISSUE_STAGE
    }
}

// ---------------------------------------------------------------------------
// Local windowed attention; writes ctx directly as bf16 hi/lo pair.
// ---------------------------------------------------------------------------
__global__ __launch_bounds__(128)
void local_attn(const float* __restrict__ q, const float* __restrict__ k,
                const float* __restrict__ v,
                __nv_bfloat16* __restrict__ ch, __nv_bfloat16* __restrict__ cl)
{
    const int bt   = blockIdx.x;
    const int t    = bt & (TT - 1);
    const int tid  = threadIdx.x;
    const int warp = tid >> 5;
    const int lane = tid & 31;

    __shared__ float red[WW][4];
    __shared__ float wgt[WW];

    const float* qrow = q + (size_t)bt * CC;
    float qreg[8];
#pragma unroll
    for (int i = 0; i < 8; i++) qreg[i] = qrow[tid + i * 128];

#pragma unroll
    for (int w = 0; w < WW; w++) {
        const int dt = w - HALF;
        const int tt = t + dt;
        float p = 0.f;
        if (tt >= 0 && tt < TT) {
            const float* krow = k + (size_t)(bt + dt) * CC;
#pragma unroll
            for (int i = 0; i < 8; i++) p += qreg[i] * krow[tid + i * 128];
        }
#pragma unroll
        for (int o = 16; o; o >>= 1) p += __shfl_xor_sync(0xffffffffu, p, o);
        if (lane == 0) red[w][warp] = p;
    }
    __syncthreads();

    if (tid == 0) {
        float s[WW];
        float mx = -1e30f;
#pragma unroll
        for (int w = 0; w < WW; w++) {
            const int tt = t + w - HALF;
            if (tt >= 0 && tt < TT) {
                s[w] = (red[w][0] + red[w][1] + red[w][2] + red[w][3]) * 0.03125f;
                mx = fmaxf(mx, s[w]);
            } else {
                s[w] = -3.0e38f;
            }
        }
        float sum = 0.f;
#pragma unroll
        for (int w = 0; w < WW; w++) {
            float e = (s[w] > -1.0e38f) ? expf(s[w] - mx) : 0.f;
            wgt[w] = e;
            sum += e;
        }
        const float inv = 1.f / sum;
#pragma unroll
        for (int w = 0; w < WW; w++) wgt[w] *= inv;
    }
    __syncthreads();

    float acc[8];
#pragma unroll
    for (int i = 0; i < 8; i++) acc[i] = 0.f;

#pragma unroll
    for (int w = 0; w < WW; w++) {
        const int dt = w - HALF;
        const int tt = t + dt;
        if (tt < 0 || tt >= TT) continue;
        const float a = wgt[w];
        const float* vrow = v + (size_t)(bt + dt) * CC;
#pragma unroll
        for (int i = 0; i < 8; i++) acc[i] += a * vrow[tid + i * 128];
    }

    __nv_bfloat16* hrow = ch + (size_t)bt * CC;
    __nv_bfloat16* lrow = cl + (size_t)bt * CC;
#pragma unroll
    for (int i = 0; i < 8; i++) {
        __nv_bfloat16 h = __float2bfloat16(acc[i]);
        __nv_bfloat16 l = __float2bfloat16(acc[i] - __bfloat162float(h));
        hrow[tid + i * 128] = h;
        lrow[tid + i * 128] = l;
    }
}

// ---------------------------------------------------------------------------
// Launch (6 launches; indices 3 and 5 are the GEMMs, for ncu capture)
// ---------------------------------------------------------------------------
extern "C" void kernel_launch(void* const* d_in, const int* in_sizes, int n_in,
                              void* d_out, int out_size)
{
    const float* x  = (const float*)d_in[0];
    const float* Wq = (const float*)d_in[1];
    const float* bq = (const float*)d_in[2];
    const float* Wk = (const float*)d_in[3];
    const float* bk = (const float*)d_in[4];
    const float* Wv = (const float*)d_in[5];
    const float* bv = (const float*)d_in[6];
    const float* Wo = (const float*)d_in[7];
    const float* bo = (const float*)d_in[8];

    float *q, *k, *v;
    __nv_bfloat16 *xh, *xl, *ch, *cl, *wh, *wl;
    cudaGetSymbolAddress((void**)&q,   g_q);
    cudaGetSymbolAddress((void**)&k,   g_k);
    cudaGetSymbolAddress((void**)&v,   g_v);
    cudaGetSymbolAddress((void**)&xh,  g_x_hi);
    cudaGetSymbolAddress((void**)&xl,  g_x_lo);
    cudaGetSymbolAddress((void**)&ch,  g_ctx_hi);
    cudaGetSymbolAddress((void**)&cl,  g_ctx_lo);
    cudaGetSymbolAddress((void**)&wh,  g_w_hi);
    cudaGetSymbolAddress((void**)&wl,  g_w_lo);

    cudaFuncSetAttribute(gemm_bf16x3, cudaFuncAttributeMaxDynamicSharedMemorySize, GEMM_SMEM);

    const int nx4 = MM * CC / 4;
    const int nw4 = CC * CC / 4;
    const size_t WSZ = (size_t)CC * CC;

    // 0: split x
    split_bf16<<<dim3(nx4 / 256, 1), 256>>>(x, x, x, xh, xl, nx4);
    // 1: split Wq, Wk, Wv  -> wh/wl segments 0..2
    split_bf16<<<dim3(nw4 / 256, 3), 256>>>(Wq, Wk, Wv, wh, wl, nw4);
    // 2: split Wo -> segment 3
    split_bf16<<<dim3(nw4 / 256, 1), 256>>>(Wo, Wo, Wo, wh + 3 * WSZ, wl + 3 * WSZ, nw4);
    // 3: fused QKV GEMM (persistent, 3072 tiles, nblk=48)
    gemm_bf16x3<<<GRID_PERSIST, 256, GEMM_SMEM>>>(xh, xl, wh, wl,
                                                  bq, bk, bv, q, k, v,
                                                  (MM / BM) * 48, 48);
    // 4: attention (writes ctx hi/lo)
    local_attn<<<MM, 128>>>(q, k, v, ch, cl);
    // 5: output projection (persistent, 1024 tiles, nblk=16)
    gemm_bf16x3<<<GRID_PERSIST, 256, GEMM_SMEM>>>(ch, cl, wh + 3 * WSZ, wl + 3 * WSZ,
                                                  bo, bo, bo,
                                                  (float*)d_out, (float*)d_out, (float*)d_out,
                                                  (MM / BM) * 16, 16);
}